// round 6
// baseline (speedup 1.0000x reference)
#include <cuda_runtime.h>
#include <cstdint>

#define BB   128
#define TT   500
#define NIN  700
#define NH   200
#define NOUT 20
#define NROWS (BB*TT)          // 64000
#define CAP  256               // max active inputs per row

// -------- scratch (static __device__ allocations: allowed) -----------------
__device__ unsigned short g_idx[(size_t)NROWS * CAP];
__device__ int            g_cnt[NROWS];
__device__ float          g_ff[(size_t)NROWS * NH];     // cur1_ff = x@W1^T + b1

// ===========================================================================
// P0: compact active input indices per (b,t) row. DRAM-bound (~35us floor).
// ===========================================================================
__global__ __launch_bounds__(256) void k_compact(const float* __restrict__ x)
{
    int wid  = threadIdx.x >> 5, lane = threadIdx.x & 31;
    int row  = blockIdx.x * 8 + wid;
    if (row >= NROWS) return;
    const float* xr = x + (size_t)row * NIN;
    unsigned short* out = g_idx + (size_t)row * CAP;
    unsigned lt = (1u << lane) - 1u;
    int cnt = 0;
#pragma unroll
    for (int c = 0; c < (NIN + 31) / 32; c++) {
        int i = c * 32 + lane;
        float v = (i < NIN) ? xr[i] : 0.f;
        bool a = v > 0.5f;
        unsigned m = __ballot_sync(0xffffffffu, a);
        if (a) {
            int pos = cnt + __popc(m & lt);
            if (pos < CAP) out[pos] = (unsigned short)i;
        }
        cnt += __popc(m);
    }
    if (lane == 0) g_cnt[row] = (cnt < CAP) ? cnt : CAP;
}

// ===========================================================================
// P1: cur1_ff[row][h] = sum over active n of W1[h][n], + b1[h].
// (UNCHANGED from R5 baseline for clean differential timing.)
// ===========================================================================
#define P1_HC     50
#define P1_STRIDE 52
#define P1_SMEM   (NIN * P1_STRIDE * 4)
#define P1_GROUPS 128
#define P1_RPC    (NROWS / P1_GROUPS)

__global__ __launch_bounds__(256) void k_ff(const float* __restrict__ W1,
                                            const float* __restrict__ b1)
{
    extern __shared__ float s[];
    int h0 = blockIdx.x * P1_HC;
    for (int i = threadIdx.x; i < P1_HC * NIN; i += 256) {
        int hh = i / NIN, n = i - hh * NIN;
        s[n * P1_STRIDE + hh] = W1[(h0 + hh) * NIN + n];
    }
    __syncthreads();

    int wid = threadIdx.x >> 5, lane = threadIdx.x & 31;
    int hh2 = 2 * lane;
    bool act = (lane < 25);
    float bb0 = 0.f, bb1 = 0.f;
    if (act) { bb0 = b1[h0 + hh2]; bb1 = b1[h0 + hh2 + 1]; }

    int base = blockIdx.y * P1_RPC;
    int lim  = base + P1_RPC; if (lim > NROWS) lim = NROWS;

    for (int row = base + wid; row < lim; row += 8) {
        int cnt = g_cnt[row];
        const unsigned short* lp = g_idx + (size_t)row * CAP;
        float c0a = 0.f, c1a = 0.f, c0b = 0.f, c1b = 0.f;
        for (int i0 = 0; i0 < cnt; i0 += 32) {
            int idx = 0;
            if (i0 + lane < cnt) idx = lp[i0 + lane];
            int kmax = cnt - i0; if (kmax > 32) kmax = 32;
#pragma unroll 8
            for (int k = 0; k < kmax; k++) {
                int j = __shfl_sync(0xffffffffu, idx, k);
                if (act) {
                    float2 v = *(const float2*)&s[j * P1_STRIDE + hh2];
                    if (k & 1) { c0b += v.x; c1b += v.y; }
                    else       { c0a += v.x; c1a += v.y; }
                }
            }
        }
        if (act) {
            float2 o; o.x = (c0a + c0b) + bb0; o.y = (c1a + c1b) + bb1;
            *(float2*)&g_ff[(size_t)row * NH + h0 + hh2] = o;
        }
    }
}

// ===========================================================================
// P2: recurrent scan. (UNCHANGED from R5 baseline; launched TWICE this round
// for differential timing: dur_R6 - dur_R5 = T_snn. Idempotent by design.)
// ===========================================================================
#define SEG 72
#define OFF_W2    (201*NH)
#define OFF_LIST  (OFF_W2 + 201*NOUT)
#define OFF_CNT   (OFF_LIST + 2*4*SEG)
#define OFF_P2    (OFF_CNT + 8)
#define OFF_P1    (OFF_P2 + 4*NOUT)
#define P2_SMEM   ((OFF_P1 + 3*NH) * 4)

__global__ __launch_bounds__(512) void k_snn(
    const float* __restrict__ Wfb,  const float* __restrict__ bfb,
    const float* __restrict__ W2,   const float* __restrict__ b2,
    const float* __restrict__ alpha1, const float* __restrict__ beta1,
    const float* __restrict__ thr1,
    const float* __restrict__ alpha2, const float* __restrict__ beta2,
    const float* __restrict__ thr2,
    float* __restrict__ out)
{
    extern __shared__ float sm[];
    float* sWfb  = sm;
    float* sW2   = sm + OFF_W2;
    int*   slist = (int*)(sm + OFF_LIST);
    int*   scnt  = (int*)(sm + OFF_CNT);
    float* spart2= sm + OFF_P2;
    float* spart1= sm + OFF_P1;

    int tid = threadIdx.x, lane = tid & 31;
    int g = tid >> 7, tid_l = tid & 127;
    int wg = (tid_l) >> 5;
    int b = blockIdx.x;

    for (int i = tid; i < NH * NH; i += 512) {
        int h = i / NH, j = i - h * NH;
        sWfb[j * NH + h] = Wfb[i];
    }
    for (int i = tid; i < NH; i += 512) sWfb[200 * NH + i] = 0.f;
    for (int i = tid; i < NOUT * NH; i += 512) {
        int o = i / NH, j = i - o * NH;
        sW2[j * NOUT + o] = W2[i];
    }
    for (int i = tid; i < NOUT; i += 512) sW2[200 * NOUT + i] = 0.f;
    if (tid < 8) scnt[tid] = 0;

    float syn0 = 0.f, syn1v = 0.f, mem0 = 0.f, mem1v = 0.f;
    float a0 = 0.f, a1 = 0.f, be0 = 0.f, be1 = 0.f;
    float th0 = 1.f, th1 = 1.f, bf0 = 0.f, bf1 = 0.f;
    const float* ffp = g_ff;
    if (g == 0 && tid_l < 100) {
        int h = 2 * tid_l;
        a0 = alpha1[h]; a1 = alpha1[h + 1];
        be0 = beta1[h]; be1 = beta1[h + 1];
        th0 = thr1[h];  th1 = thr1[h + 1];
        bf0 = bfb[h];   bf1 = bfb[h + 1];
        ffp = g_ff + (size_t)b * TT * NH + h;
    }
    float s2 = 0.f, m2 = 0.f;
    float a2l = 0.f, be2l = 0.f, th2l = 1.f, b2l = 0.f;
    float rmax = __int_as_float(0xff800000u);
    if (g == 1 && tid_l < 20) {
        a2l = alpha2[tid_l]; be2l = beta2[tid_l]; th2l = thr2[tid_l]; b2l = b2[tid_l];
    }
    __syncthreads();

    float ff0 = 0.f, ff1 = 0.f, nf0 = 0.f, nf1 = 0.f;
    if (g == 0 && tid_l < 100) { float2 v = *(const float2*)ffp; ff0 = v.x; ff1 = v.y; }

    const float2* wf2 = (const float2*)sWfb;

    for (int t = 0; t < TT; t++) {
        int p = t & 1, q = p ^ 1;

        if (g == 0 && tid_l < 100 && t + 1 < TT) {
            float2 v = *(const float2*)(ffp + (size_t)(t + 1) * NH);
            nf0 = v.x; nf1 = v.y;
        }

        float c0 = 0.f, c1 = 0.f;
        int cseg = scnt[p * 4 + g];
        if (tid_l < 100) {
            const int4* p4 = (const int4*)&slist[(p * 4 + g) * SEG];
            int it = (cseg + 3) >> 2;
            float d0 = 0.f, d1 = 0.f;
#pragma unroll 2
            for (int k = 0; k < it; k++) {
                int4 jj = p4[k];
                float2 v0 = wf2[jj.x * 100 + tid_l];
                float2 v1 = wf2[jj.y * 100 + tid_l];
                float2 v2 = wf2[jj.z * 100 + tid_l];
                float2 v3 = wf2[jj.w * 100 + tid_l];
                c0 += v0.x + v1.x;  d0 += v2.x + v3.x;
                c1 += v0.y + v1.y;  d1 += v2.y + v3.y;
            }
            c0 += d0; c1 += d1;
            if (g > 0) {
                float2 o; o.x = c0; o.y = c1;
                ((float2*)spart1)[(g - 1) * 100 + tid_l] = o;
            }
        } else if (wg == 3 && lane >= 4 && lane < 24) {
            int o = lane - 4;
            float pp = 0.f, qq = 0.f;
            const int4* p4 = (const int4*)&slist[(p * 4 + g) * SEG];
            int it = (cseg + 3) >> 2;
            for (int k = 0; k < it; k++) {
                int4 jj = p4[k];
                pp += sW2[jj.x * NOUT + o] + sW2[jj.y * NOUT + o];
                qq += sW2[jj.z * NOUT + o] + sW2[jj.w * NOUT + o];
            }
            spart2[g * NOUT + o] = pp + qq;
        }
        __syncthreads();

        bool sp0 = false, sp1 = false;
        if (g == 0) {
            if (tid_l < 100) {
                float2 pa = ((const float2*)spart1)[tid_l];
                float2 pb = ((const float2*)spart1)[100 + tid_l];
                float2 pc = ((const float2*)spart1)[200 + tid_l];
                c0 += (pa.x + pb.x) + pc.x + ff0 + bf0;
                c1 += (pa.y + pb.y) + pc.y + ff1 + bf1;
                syn0  = a0 * syn0  + c0;
                syn1v = a1 * syn1v + c1;
                float r0 = (mem0  > th0) ? th0 : 0.f;
                float r1 = (mem1v > th1) ? th1 : 0.f;
                mem0  = be0 * mem0  + syn0  - r0;
                mem1v = be1 * mem1v + syn1v - r1;
                sp0 = mem0  > th0;
                sp1 = mem1v > th1;
            }
            unsigned m0 = __ballot_sync(0xffffffffu, sp0);
            unsigned m1 = __ballot_sync(0xffffffffu, sp1);
            int* seg = &slist[(q * 4 + wg) * SEG];
            unsigned lt = (1u << lane) - 1u;
            int c0n = __popc(m0);
            int cnt = c0n + __popc(m1);
            if (sp0) seg[__popc(m0 & lt)]       = 2 * tid_l;
            if (sp1) seg[c0n + __popc(m1 & lt)] = 2 * tid_l + 1;
            if (lane == 0) {
                scnt[q * 4 + wg] = cnt;
                int cp = cnt;
                while (cp & 3) seg[cp++] = 200;
            }
        }
        if (g == 1 && tid_l < 20 && t > 0) {
            float c2 = b2l + (spart2[tid_l] + spart2[NOUT + tid_l]) +
                             (spart2[2 * NOUT + tid_l] + spart2[3 * NOUT + tid_l]);
            s2 = a2l * s2 + c2;
            float r2 = (m2 > th2l) ? th2l : 0.f;
            m2 = be2l * m2 + s2 - r2;
            rmax = fmaxf(rmax, m2);
        }
        __syncthreads();
        ff0 = nf0; ff1 = nf1;
    }

    if (g == 1 && tid_l < 20) {
        int pbuf = TT & 1;
        float pp = 0.f;
        for (int w = 0; w < 4; w++) {
            int c = scnt[pbuf * 4 + w];
            const int4* p4 = (const int4*)&slist[(pbuf * 4 + w) * SEG];
            int it = (c + 3) >> 2;
            for (int k = 0; k < it; k++) {
                int4 jj = p4[k];
                pp += (sW2[jj.x * NOUT + tid_l] + sW2[jj.y * NOUT + tid_l]) +
                      (sW2[jj.z * NOUT + tid_l] + sW2[jj.w * NOUT + tid_l]);
            }
        }
        float c2 = b2l + pp;
        s2 = a2l * s2 + c2;
        float r2 = (m2 > th2l) ? th2l : 0.f;
        m2 = be2l * m2 + s2 - r2;
        rmax = fmaxf(rmax, m2);
    }
    __syncthreads();

    if ((tid >> 5) == 4) {
        float v = (lane < 20) ? rmax : __int_as_float(0xff800000u);
#pragma unroll
        for (int d = 16; d; d >>= 1) v = fmaxf(v, __shfl_xor_sync(0xffffffffu, v, d));
        float e = (lane < 20) ? expf(rmax - v) : 0.f;
        float ssum = e;
#pragma unroll
        for (int d = 16; d; d >>= 1) ssum += __shfl_xor_sync(0xffffffffu, ssum, d);
        if (lane < 20) out[b * NOUT + lane] = e / ssum;
    }
}

// ===========================================================================
extern "C" void kernel_launch(void* const* d_in, const int* in_sizes, int n_in,
                              void* d_out, int out_size)
{
    const float* x      = (const float*)d_in[0];
    const float* W1     = (const float*)d_in[1];
    const float* b1     = (const float*)d_in[2];
    const float* Wfb    = (const float*)d_in[3];
    const float* bfb    = (const float*)d_in[4];
    const float* W2     = (const float*)d_in[5];
    const float* b2     = (const float*)d_in[6];
    const float* alpha1 = (const float*)d_in[7];
    const float* beta1  = (const float*)d_in[8];
    const float* thr1   = (const float*)d_in[9];
    const float* alpha2 = (const float*)d_in[10];
    const float* beta2  = (const float*)d_in[11];
    const float* thr2   = (const float*)d_in[12];
    float* out = (float*)d_out;

    cudaFuncSetAttribute(k_ff,  cudaFuncAttributeMaxDynamicSharedMemorySize, P1_SMEM);
    cudaFuncSetAttribute(k_snn, cudaFuncAttributeMaxDynamicSharedMemorySize, P2_SMEM);

    k_compact<<<NROWS / 8, 256>>>(x);
    k_ff<<<dim3(4, P1_GROUPS), 256, P1_SMEM>>>(W1, b1);
    // DIFFERENTIAL TIMING: k_snn launched twice (idempotent, deterministic).
    // dur_R6 - dur_R5(1587.3us) = T_snn; T_ff = 1552 - T_snn.
    k_snn<<<BB, 512, P2_SMEM>>>(Wfb, bfb, W2, b2,
                                alpha1, beta1, thr1,
                                alpha2, beta2, thr2, out);
    k_snn<<<BB, 512, P2_SMEM>>>(Wfb, bfb, W2, b2,
                                alpha1, beta1, thr1,
                                alpha2, beta2, thr2, out);
}

// round 7
// speedup vs baseline: 2.1370x; 2.1370x over previous
#include <cuda_runtime.h>
#include <cstdint>

#define BB   128
#define TT   500
#define NIN  700
#define NH   200
#define NOUT 20
#define NROWS (BB*TT)          // 64000
#define CAP  256               // max active inputs per row (x4-padded with 700)

// -------- scratch (static __device__ allocations: allowed) -----------------
__device__ unsigned short g_idx[(size_t)NROWS * CAP];
__device__ int            g_cnt[NROWS];
__device__ float          g_ff[(size_t)NROWS * NH];     // cur1_ff = x@W1^T + b1

// ===========================================================================
// P0: compact active input indices per (b,t) row; pad list to x4 with 700
// (the zero row in k_ff's smem weight tile). DRAM-bound (~35us floor).
// ===========================================================================
__global__ __launch_bounds__(256) void k_compact(const float* __restrict__ x)
{
    int wid  = threadIdx.x >> 5, lane = threadIdx.x & 31;
    int row  = blockIdx.x * 8 + wid;
    if (row >= NROWS) return;
    const float* xr = x + (size_t)row * NIN;
    unsigned short* out = g_idx + (size_t)row * CAP;
    unsigned lt = (1u << lane) - 1u;
    int cnt = 0;
#pragma unroll
    for (int c = 0; c < (NIN + 31) / 32; c++) {
        int i = c * 32 + lane;
        float v = (i < NIN) ? xr[i] : 0.f;
        bool a = v > 0.5f;
        unsigned m = __ballot_sync(0xffffffffu, a);
        if (a) {
            int pos = cnt + __popc(m & lt);
            if (pos < CAP) out[pos] = (unsigned short)i;
        }
        cnt += __popc(m);
    }
    if (lane == 0) {
        int c = (cnt < CAP) ? cnt : CAP;
        g_cnt[row] = c;
        int cp = c;
        while ((cp & 3) && cp < CAP) out[cp++] = 700;   // pad -> zero row
    }
}

// ===========================================================================
// P1 (REWRITTEN): cur1_ff[row][h] = sum over active n of W1[h][n], + b1[h].
// 512 threads (16 warps = 4/SMSP). W1^T slice [701 x 52] in smem (row 700=0).
// Per warp: prefetch next row's cnt + first 128 indices (LDG.64) while
// consuming current row via UNIFORM LDS of packed uint2 (4 idx/load).
// No SHFL anywhere in the hot loop.
// ===========================================================================
#define P1_HC     50
#define P1_STRIDE 52
#define P1_WSLOT  64                             // uint2 per warp buffer (256 idx)
#define OFF_BUF   (701 * P1_STRIDE)              // floats; 8B-aligned (145808 B)
#define P1_SMEM   ((OFF_BUF + 16 * P1_WSLOT * 2) * 4)   // + 16 warp bufs (8KB)
#define P1_GROUPS 128
#define P1_RPC    (NROWS / P1_GROUPS)            // 500

__global__ __launch_bounds__(512) void k_ff(const float* __restrict__ W1,
                                            const float* __restrict__ b1)
{
    extern __shared__ float s[];
    int tid = threadIdx.x, wid = tid >> 5, lane = tid & 31;
    int h0 = blockIdx.x * P1_HC;

    // s[n*52 + hh] = W1[(h0+hh)*700 + n]; row n=700 = zeros
    for (int i = tid; i < P1_HC * NIN; i += 512) {
        int hh = i / NIN, n = i - hh * NIN;
        s[n * P1_STRIDE + hh] = W1[(h0 + hh) * NIN + n];
    }
    for (int i = tid; i < P1_STRIDE; i += 512) s[700 * P1_STRIDE + i] = 0.f;
    __syncthreads();

    uint2* swbuf = (uint2*)(s + OFF_BUF) + wid * P1_WSLOT;  // this warp's 256-idx slot
    const uint2* sbuf2 = (const uint2*)swbuf;

    int hh2 = 2 * lane;
    bool act = (lane < 25);
    float bb0 = 0.f, bb1 = 0.f;
    if (act) { bb0 = b1[h0 + hh2]; bb1 = b1[h0 + hh2 + 1]; }

    int base = blockIdx.y * P1_RPC;
    int lim  = base + P1_RPC; if (lim > NROWS) lim = NROWS;

    int row = base + wid;
    if (row >= lim) return;

    // prologue: load row's cnt + first 128 indices
    int  cnt_c = g_cnt[row];
    uint2 rA   = ((const uint2*)(g_idx + (size_t)row * CAP))[lane];

    while (row < lim) {
        int rn = row + 16;
        int  cnt_n = 0;
        uint2 nA = make_uint2(0u, 0u);
        if (rn < lim) {                           // prefetch next row
            cnt_n = g_cnt[rn];
            nA = ((const uint2*)(g_idx + (size_t)rn * CAP))[lane];
        }

        // stage current row's indices into warp smem buffer
        swbuf[lane] = rA;                         // elements 0..127
        if (cnt_c > 128)                          // ~never (mean 70, sd 8)
            swbuf[32 + lane] = ((const uint2*)(g_idx + (size_t)row * CAP))[32 + lane];
        __syncwarp();

        float c0a = 0.f, c1a = 0.f, c0b = 0.f, c1b = 0.f;
        int it = (cnt_c + 3) >> 2;                // quads (x4-padded with 700)
#pragma unroll 2
        for (int k = 0; k < it; k++) {
            uint2 u = sbuf2[k];                   // uniform LDS: 4 indices
            int j0 = u.x & 0xffff, j1 = u.x >> 16;
            int j2 = u.y & 0xffff, j3 = u.y >> 16;
            if (act) {
                float2 v0 = *(const float2*)&s[j0 * P1_STRIDE + hh2];
                float2 v1 = *(const float2*)&s[j1 * P1_STRIDE + hh2];
                float2 v2 = *(const float2*)&s[j2 * P1_STRIDE + hh2];
                float2 v3 = *(const float2*)&s[j3 * P1_STRIDE + hh2];
                c0a += v0.x + v1.x;  c0b += v2.x + v3.x;
                c1a += v0.y + v1.y;  c1b += v2.y + v3.y;
            }
        }
        if (act) {
            float2 o; o.x = (c0a + c0b) + bb0; o.y = (c1a + c1b) + bb1;
            *(float2*)&g_ff[(size_t)row * NH + h0 + hh2] = o;
        }
        __syncwarp();                             // buffer reads done before re-stage

        row = rn; cnt_c = cnt_n; rA = nA;
    }
}

// ===========================================================================
// P2: recurrent scan. UNCHANGED from R5 baseline (774us measured; next target).
// ===========================================================================
#define SEG 72
#define OFF_W2    (201*NH)
#define OFF_LIST  (OFF_W2 + 201*NOUT)
#define OFF_CNT   (OFF_LIST + 2*4*SEG)
#define OFF_P2    (OFF_CNT + 8)
#define OFF_P1    (OFF_P2 + 4*NOUT)
#define P2_SMEM   ((OFF_P1 + 3*NH) * 4)

__global__ __launch_bounds__(512) void k_snn(
    const float* __restrict__ Wfb,  const float* __restrict__ bfb,
    const float* __restrict__ W2,   const float* __restrict__ b2,
    const float* __restrict__ alpha1, const float* __restrict__ beta1,
    const float* __restrict__ thr1,
    const float* __restrict__ alpha2, const float* __restrict__ beta2,
    const float* __restrict__ thr2,
    float* __restrict__ out)
{
    extern __shared__ float sm[];
    float* sWfb  = sm;
    float* sW2   = sm + OFF_W2;
    int*   slist = (int*)(sm + OFF_LIST);
    int*   scnt  = (int*)(sm + OFF_CNT);
    float* spart2= sm + OFF_P2;
    float* spart1= sm + OFF_P1;

    int tid = threadIdx.x, lane = tid & 31;
    int g = tid >> 7, tid_l = tid & 127;
    int wg = (tid_l) >> 5;
    int b = blockIdx.x;

    for (int i = tid; i < NH * NH; i += 512) {
        int h = i / NH, j = i - h * NH;
        sWfb[j * NH + h] = Wfb[i];
    }
    for (int i = tid; i < NH; i += 512) sWfb[200 * NH + i] = 0.f;
    for (int i = tid; i < NOUT * NH; i += 512) {
        int o = i / NH, j = i - o * NH;
        sW2[j * NOUT + o] = W2[i];
    }
    for (int i = tid; i < NOUT; i += 512) sW2[200 * NOUT + i] = 0.f;
    if (tid < 8) scnt[tid] = 0;

    float syn0 = 0.f, syn1v = 0.f, mem0 = 0.f, mem1v = 0.f;
    float a0 = 0.f, a1 = 0.f, be0 = 0.f, be1 = 0.f;
    float th0 = 1.f, th1 = 1.f, bf0 = 0.f, bf1 = 0.f;
    const float* ffp = g_ff;
    if (g == 0 && tid_l < 100) {
        int h = 2 * tid_l;
        a0 = alpha1[h]; a1 = alpha1[h + 1];
        be0 = beta1[h]; be1 = beta1[h + 1];
        th0 = thr1[h];  th1 = thr1[h + 1];
        bf0 = bfb[h];   bf1 = bfb[h + 1];
        ffp = g_ff + (size_t)b * TT * NH + h;
    }
    float s2 = 0.f, m2 = 0.f;
    float a2l = 0.f, be2l = 0.f, th2l = 1.f, b2l = 0.f;
    float rmax = __int_as_float(0xff800000u);
    if (g == 1 && tid_l < 20) {
        a2l = alpha2[tid_l]; be2l = beta2[tid_l]; th2l = thr2[tid_l]; b2l = b2[tid_l];
    }
    __syncthreads();

    float ff0 = 0.f, ff1 = 0.f, nf0 = 0.f, nf1 = 0.f;
    if (g == 0 && tid_l < 100) { float2 v = *(const float2*)ffp; ff0 = v.x; ff1 = v.y; }

    const float2* wf2 = (const float2*)sWfb;

    for (int t = 0; t < TT; t++) {
        int p = t & 1, q = p ^ 1;

        if (g == 0 && tid_l < 100 && t + 1 < TT) {
            float2 v = *(const float2*)(ffp + (size_t)(t + 1) * NH);
            nf0 = v.x; nf1 = v.y;
        }

        float c0 = 0.f, c1 = 0.f;
        int cseg = scnt[p * 4 + g];
        if (tid_l < 100) {
            const int4* p4 = (const int4*)&slist[(p * 4 + g) * SEG];
            int it = (cseg + 3) >> 2;
            float d0 = 0.f, d1 = 0.f;
#pragma unroll 2
            for (int k = 0; k < it; k++) {
                int4 jj = p4[k];
                float2 v0 = wf2[jj.x * 100 + tid_l];
                float2 v1 = wf2[jj.y * 100 + tid_l];
                float2 v2 = wf2[jj.z * 100 + tid_l];
                float2 v3 = wf2[jj.w * 100 + tid_l];
                c0 += v0.x + v1.x;  d0 += v2.x + v3.x;
                c1 += v0.y + v1.y;  d1 += v2.y + v3.y;
            }
            c0 += d0; c1 += d1;
            if (g > 0) {
                float2 o; o.x = c0; o.y = c1;
                ((float2*)spart1)[(g - 1) * 100 + tid_l] = o;
            }
        } else if (wg == 3 && lane >= 4 && lane < 24) {
            int o = lane - 4;
            float pp = 0.f, qq = 0.f;
            const int4* p4 = (const int4*)&slist[(p * 4 + g) * SEG];
            int it = (cseg + 3) >> 2;
            for (int k = 0; k < it; k++) {
                int4 jj = p4[k];
                pp += sW2[jj.x * NOUT + o] + sW2[jj.y * NOUT + o];
                qq += sW2[jj.z * NOUT + o] + sW2[jj.w * NOUT + o];
            }
            spart2[g * NOUT + o] = pp + qq;
        }
        __syncthreads();

        bool sp0 = false, sp1 = false;
        if (g == 0) {
            if (tid_l < 100) {
                float2 pa = ((const float2*)spart1)[tid_l];
                float2 pb = ((const float2*)spart1)[100 + tid_l];
                float2 pc = ((const float2*)spart1)[200 + tid_l];
                c0 += (pa.x + pb.x) + pc.x + ff0 + bf0;
                c1 += (pa.y + pb.y) + pc.y + ff1 + bf1;
                syn0  = a0 * syn0  + c0;
                syn1v = a1 * syn1v + c1;
                float r0 = (mem0  > th0) ? th0 : 0.f;
                float r1 = (mem1v > th1) ? th1 : 0.f;
                mem0  = be0 * mem0  + syn0  - r0;
                mem1v = be1 * mem1v + syn1v - r1;
                sp0 = mem0  > th0;
                sp1 = mem1v > th1;
            }
            unsigned m0 = __ballot_sync(0xffffffffu, sp0);
            unsigned m1 = __ballot_sync(0xffffffffu, sp1);
            int* seg = &slist[(q * 4 + wg) * SEG];
            unsigned lt = (1u << lane) - 1u;
            int c0n = __popc(m0);
            int cnt = c0n + __popc(m1);
            if (sp0) seg[__popc(m0 & lt)]       = 2 * tid_l;
            if (sp1) seg[c0n + __popc(m1 & lt)] = 2 * tid_l + 1;
            if (lane == 0) {
                scnt[q * 4 + wg] = cnt;
                int cp = cnt;
                while (cp & 3) seg[cp++] = 200;
            }
        }
        if (g == 1 && tid_l < 20 && t > 0) {
            float c2 = b2l + (spart2[tid_l] + spart2[NOUT + tid_l]) +
                             (spart2[2 * NOUT + tid_l] + spart2[3 * NOUT + tid_l]);
            s2 = a2l * s2 + c2;
            float r2 = (m2 > th2l) ? th2l : 0.f;
            m2 = be2l * m2 + s2 - r2;
            rmax = fmaxf(rmax, m2);
        }
        __syncthreads();
        ff0 = nf0; ff1 = nf1;
    }

    if (g == 1 && tid_l < 20) {
        int pbuf = TT & 1;
        float pp = 0.f;
        for (int w = 0; w < 4; w++) {
            int c = scnt[pbuf * 4 + w];
            const int4* p4 = (const int4*)&slist[(pbuf * 4 + w) * SEG];
            int it = (c + 3) >> 2;
            for (int k = 0; k < it; k++) {
                int4 jj = p4[k];
                pp += (sW2[jj.x * NOUT + tid_l] + sW2[jj.y * NOUT + tid_l]) +
                      (sW2[jj.z * NOUT + tid_l] + sW2[jj.w * NOUT + tid_l]);
            }
        }
        float c2 = b2l + pp;
        s2 = a2l * s2 + c2;
        float r2 = (m2 > th2l) ? th2l : 0.f;
        m2 = be2l * m2 + s2 - r2;
        rmax = fmaxf(rmax, m2);
    }
    __syncthreads();

    if ((tid >> 5) == 4) {
        float v = (lane < 20) ? rmax : __int_as_float(0xff800000u);
#pragma unroll
        for (int d = 16; d; d >>= 1) v = fmaxf(v, __shfl_xor_sync(0xffffffffu, v, d));
        float e = (lane < 20) ? expf(rmax - v) : 0.f;
        float ssum = e;
#pragma unroll
        for (int d = 16; d; d >>= 1) ssum += __shfl_xor_sync(0xffffffffu, ssum, d);
        if (lane < 20) out[b * NOUT + lane] = e / ssum;
    }
}

// ===========================================================================
extern "C" void kernel_launch(void* const* d_in, const int* in_sizes, int n_in,
                              void* d_out, int out_size)
{
    const float* x      = (const float*)d_in[0];
    const float* W1     = (const float*)d_in[1];
    const float* b1     = (const float*)d_in[2];
    const float* Wfb    = (const float*)d_in[3];
    const float* bfb    = (const float*)d_in[4];
    const float* W2     = (const float*)d_in[5];
    const float* b2     = (const float*)d_in[6];
    const float* alpha1 = (const float*)d_in[7];
    const float* beta1  = (const float*)d_in[8];
    const float* thr1   = (const float*)d_in[9];
    const float* alpha2 = (const float*)d_in[10];
    const float* beta2  = (const float*)d_in[11];
    const float* thr2   = (const float*)d_in[12];
    float* out = (float*)d_out;

    cudaFuncSetAttribute(k_ff,  cudaFuncAttributeMaxDynamicSharedMemorySize, P1_SMEM);
    cudaFuncSetAttribute(k_snn, cudaFuncAttributeMaxDynamicSharedMemorySize, P2_SMEM);

    k_compact<<<NROWS / 8, 256>>>(x);
    k_ff<<<dim3(4, P1_GROUPS), 512, P1_SMEM>>>(W1, b1);
    k_snn<<<BB, 512, P2_SMEM>>>(Wfb, bfb, W2, b2,
                                alpha1, beta1, thr1,
                                alpha2, beta2, thr2, out);
}